// round 13
// baseline (speedup 1.0000x reference)
#include <cuda_runtime.h>
#include <cuda_bf16.h>
#include <cstdint>

#define NS   2048
#define NI   384
#define NC   64
#define NH   8
#define HC   64
#define TS   128          // rows per tile (= GEMM M per block)
#define NT   (NS / TS)    // 16 tiles
#define TP   65           // k_pass1 smem tile stride (scalar access only)
#define XS   72           // bf16 tile row stride (elements) — ldmatrix conflict-free
#define KS9  9            // k_attn smem row stride (floats) — conflict-free
#define FST  68           // k_out float staging stride (floats) — conflict-free f4

// k_out dynamic smem offsets (bytes) — both weight pairs resident
#define OFF_CTX  0
#define OFF_BG   256
#define OFF_BO   512
#define OFF_XHI  1024
#define OFF_XLO  (OFF_XHI + TS * XS * 2)        // 19456
#define OFF_WGH  (OFF_XLO + TS * XS * 2)        // 37888  (also m staging area)
#define OFF_WGL  (OFF_WGH + NC * XS * 2)        // 47104
#define OFF_WOH  (OFF_WGL + NC * XS * 2)        // 56320
#define OFF_WOL  (OFF_WOH + NC * XS * 2)        // 65536
#define SMEM_TOTAL_OUT (OFF_WOL + NC * XS * 2)  // 74752
// staging needs TS*FST*4 = 34816 B <= 4*9216 = 36864 B  (weights area) OK

// ---------------- scratch (device globals; no allocation) ----------------
__device__ __align__(16) float g_k[(size_t)NI * NS * 8];   // [i][s][ch]
__device__ __align__(16) float g_v[(size_t)NI * NS * 8];   // [i][s][ch]
__device__ float g_mcol[(size_t)NI * NS];                  // mask, column-major
__device__ float g_qpart[NT * NI * NC];                    // [tile][i][c]
__device__ float g_ctx[NI * HC];                           // [i][h*8+ch]
// bf16 hi/lo weights, [n][k] K-major, row stride XS
__device__ __align__(16) __nv_bfloat16 g_wgh[NC * XS];
__device__ __align__(16) __nv_bfloat16 g_wgl[NC * XS];
__device__ __align__(16) __nv_bfloat16 g_woh[NC * XS];
__device__ __align__(16) __nv_bfloat16 g_wol[NC * XS];

// ---------------- packed fp32x2 helpers (FFMA2 path, k_pass1) -------------
__device__ __forceinline__ unsigned long long pk2(float x, float y) {
    unsigned long long r;
    asm("mov.b64 %0, {%1, %2};" : "=l"(r) : "f"(x), "f"(y));
    return r;
}
__device__ __forceinline__ void upk2(unsigned long long v, float& x, float& y) {
    asm("mov.b64 {%0, %1}, %2;" : "=f"(x), "=f"(y) : "l"(v));
}
__device__ __forceinline__ unsigned long long f2fma(unsigned long long a,
                                                    unsigned long long b,
                                                    unsigned long long c) {
    unsigned long long d;
    asm("fma.rn.f32x2 %0, %1, %2, %3;" : "=l"(d) : "l"(a), "l"(b), "l"(c));
    return d;
}

// ---------------- mma.sync / ldmatrix helpers (base ISA, sm_80+) ----------
__device__ __forceinline__ uint32_t smem_u32(const void* p) {
    uint32_t a;
    asm("{ .reg .u64 t; cvta.to.shared.u64 t, %1; cvt.u32.u64 %0, t; }"
        : "=r"(a) : "l"(p));
    return a;
}
__device__ __forceinline__ void ldmx4(uint32_t* r, uint32_t addr) {
    asm volatile("ldmatrix.sync.aligned.m8n8.x4.shared.b16 {%0,%1,%2,%3}, [%4];"
                 : "=r"(r[0]), "=r"(r[1]), "=r"(r[2]), "=r"(r[3]) : "r"(addr));
}
__device__ __forceinline__ void ldmx2(uint32_t* r, uint32_t addr) {
    asm volatile("ldmatrix.sync.aligned.m8n8.x2.shared.b16 {%0,%1}, [%2];"
                 : "=r"(r[0]), "=r"(r[1]) : "r"(addr));
}
__device__ __forceinline__ void mma16816(float* d, const uint32_t* a,
                                         const uint32_t* b) {
    asm volatile(
        "mma.sync.aligned.m16n8k16.row.col.f32.bf16.bf16.f32 "
        "{%0,%1,%2,%3}, {%4,%5,%6,%7}, {%8,%9}, {%0,%1,%2,%3};"
        : "+f"(d[0]), "+f"(d[1]), "+f"(d[2]), "+f"(d[3])
        : "r"(a[0]), "r"(a[1]), "r"(a[2]), "r"(a[3]), "r"(b[0]), "r"(b[1]));
}

// 3-pass bf16-split GEMM: acc += Xh*Wh + Xh*Wl + Xl*Wh  (M=128,N=64,K=64)
__device__ __forceinline__ void gemm_bf16_split(
    uint32_t xh, uint32_t xl, uint32_t wh, uint32_t wl,
    int warp, int lane, float acc[2][8][4]) {
    const int arow = ((lane >> 3) & 1) * 8 + (lane & 7);
    const int acol = (lane >> 4) * 8;
    const int brow = lane & 7;
    const int bcol = ((lane >> 3) & 1) * 8;
#pragma unroll
    for (int ks = 0; ks < 4; ks++) {
        uint32_t ah[2][4], al[2][4];
#pragma unroll
        for (int mt = 0; mt < 2; mt++) {
            const uint32_t aoff =
                (uint32_t)(((warp * 32 + mt * 16 + arow) * XS + ks * 16 + acol) * 2);
            ldmx4(ah[mt], xh + aoff);
            ldmx4(al[mt], xl + aoff);
        }
#pragma unroll
        for (int nt = 0; nt < 8; nt++) {
            const uint32_t boff =
                (uint32_t)(((nt * 8 + brow) * XS + ks * 16 + bcol) * 2);
            uint32_t bh[2], bl[2];
            ldmx2(bh, wh + boff);
            ldmx2(bl, wl + boff);
#pragma unroll
            for (int mt = 0; mt < 2; mt++) {
                mma16816(acc[mt][nt], ah[mt], bh);
                mma16816(acc[mt][nt], ah[mt], bl);
                mma16816(acc[mt][nt], al[mt], bh);
            }
        }
    }
}

// ==========================================================================
// Kernel 1: LN + k/v projection (FFMA2) + q_global partials + mask repack.
// Block (0,0) additionally performs the one-time bf16 weight prep.
// grid (NT, NI), block TS=128. One thread = one s-row. (R11 proven config.)
// ==========================================================================
__global__ void __launch_bounds__(TS) k_pass1(
    const float* __restrict__ m, const float* __restrict__ mask,
    const float* __restrict__ gamma, const float* __restrict__ beta,
    const float* __restrict__ Wk, const float* __restrict__ Wv,
    const float* __restrict__ Wg, const float* __restrict__ Wo) {
    __shared__ float tile[TS * TP];
    __shared__ __align__(16) float sWT[NC * 16];  // [c][0..7]=Wk, [c][8..15]=Wv
    __shared__ float sg[NC], sb[NC];

    const int i  = blockIdx.y;
    const int s0 = blockIdx.x * TS;
    const int t  = threadIdx.x;

    // one block does weight prep (k_out consumes after this grid completes)
    if (blockIdx.x == 0 && blockIdx.y == 0) {
        for (int idx = t; idx < NC * NC; idx += TS) {
            const int n = idx >> 6, k = idx & 63;
            const int dst = n * XS + k;
            const float wg = Wg[idx];
            const __nv_bfloat16 gh = __float2bfloat16(wg);
            g_wgh[dst] = gh;
            g_wgl[dst] = __float2bfloat16(wg - __bfloat162float(gh));
            const float wo = Wo[idx];
            const __nv_bfloat16 oh = __float2bfloat16(wo);
            g_woh[dst] = oh;
            g_wol[dst] = __float2bfloat16(wo - __bfloat162float(oh));
        }
    }

    for (int idx = t; idx < 8 * NC; idx += TS) {
        const int j = idx >> 6, c = idx & 63;
        sWT[c * 16 + j]     = Wk[idx];
        sWT[c * 16 + 8 + j] = Wv[idx];
    }
    if (t < NC) { sg[t] = gamma[t]; sb[t] = beta[t]; }
    for (int idx = t; idx < TS * NC / 4; idx += TS) {
        const int r = idx >> 4, c4 = (idx & 15) * 4;
        const float4 v = *(const float4*)&m[((size_t)(s0 + r) * NI + i) * NC + c4];
        tile[r * TP + c4 + 0] = v.x;
        tile[r * TP + c4 + 1] = v.y;
        tile[r * TP + c4 + 2] = v.z;
        tile[r * TP + c4 + 3] = v.w;
    }
    __syncthreads();

    float s1 = 0.f, s2 = 0.f;
#pragma unroll
    for (int c = 0; c < NC; c++) {
        const float v = tile[t * TP + c];
        s1 += v; s2 += v * v;
    }
    const float mu   = s1 * (1.f / 64.f);
    const float var  = s2 * (1.f / 64.f) - mu * mu;
    const float rstd = rsqrtf(var + 1e-5f);
    const float maskv = mask[(size_t)(s0 + t) * NI + i];
    g_mcol[(size_t)i * NS + s0 + t] = maskv;

    unsigned long long ka2[4], va2[4];
#pragma unroll
    for (int j = 0; j < 4; j++) { ka2[j] = 0ull; va2[j] = 0ull; }

#pragma unroll
    for (int c = 0; c < NC; c++) {
        const float mn = (tile[t * TP + c] - mu) * rstd * sg[c] + sb[c];
        tile[t * TP + c] = mn * maskv;
        const unsigned long long mp = pk2(mn, mn);
        const ulonglong2 wk  = *(const ulonglong2*)&sWT[c * 16];
        const ulonglong2 wk1 = *(const ulonglong2*)&sWT[c * 16 + 4];
        const ulonglong2 wv  = *(const ulonglong2*)&sWT[c * 16 + 8];
        const ulonglong2 wv1 = *(const ulonglong2*)&sWT[c * 16 + 12];
        ka2[0] = f2fma(mp, wk.x,  ka2[0]);
        ka2[1] = f2fma(mp, wk.y,  ka2[1]);
        ka2[2] = f2fma(mp, wk1.x, ka2[2]);
        ka2[3] = f2fma(mp, wk1.y, ka2[3]);
        va2[0] = f2fma(mp, wv.x,  va2[0]);
        va2[1] = f2fma(mp, wv.y,  va2[1]);
        va2[2] = f2fma(mp, wv1.x, va2[2]);
        va2[3] = f2fma(mp, wv1.y, va2[3]);
    }

    float kr[8], vr[8];
#pragma unroll
    for (int j = 0; j < 4; j++) {
        upk2(ka2[j], kr[2 * j], kr[2 * j + 1]);
        upk2(va2[j], vr[2 * j], vr[2 * j + 1]);
    }
    float4* kp = (float4*)&g_k[((size_t)i * NS + s0 + t) * 8];
    float4* vp = (float4*)&g_v[((size_t)i * NS + s0 + t) * 8];
    kp[0] = make_float4(kr[0], kr[1], kr[2], kr[3]);
    kp[1] = make_float4(kr[4], kr[5], kr[6], kr[7]);
    vp[0] = make_float4(vr[0], vr[1], vr[2], vr[3]);
    vp[1] = make_float4(vr[4], vr[5], vr[6], vr[7]);
    __syncthreads();

    if (t < NC) {
        float a0 = 0.f, a1 = 0.f, a2 = 0.f, a3 = 0.f;
        for (int r = 0; r < TS; r += 4) {
            a0 += tile[(r + 0) * TP + t];
            a1 += tile[(r + 1) * TP + t];
            a2 += tile[(r + 2) * TP + t];
            a3 += tile[(r + 3) * TP + t];
        }
        g_qpart[((size_t)blockIdx.x * NI + i) * NC + t] = (a0 + a1) + (a2 + a3);
    }
}

// ==========================================================================
// Kernel 2: q projection (merged) + smem-staged warp-per-head attention.
// grid NI, block 256 (8 warps = 8 heads). One-pass softmax (logits tiny).
// ==========================================================================
__global__ void __launch_bounds__(256) k_attn(const float* __restrict__ Wq) {
    __shared__ float sq[HC];
    __shared__ float sqg[NC];
    __shared__ float sden[256];
    __shared__ float sk[256 * KS9];
    __shared__ float sv[256 * KS9];
    __shared__ float smk[256];

    const int i = blockIdx.x;
    const int t = threadIdx.x;
    const int h = t >> 5, lane = t & 31;

    // ---- q projection prologue (merged k_q) ----
    float dsum = 0.f;
    for (int s = t; s < NS; s += 256) dsum += g_mcol[(size_t)i * NS + s];
    sden[t] = dsum;
    if (t < NC) {
        float acc = 0.f;
        for (int tt = 0; tt < NT; tt++)
            acc += g_qpart[((size_t)tt * NI + i) * NC + t];
        sqg[t] = acc;
    }
    __syncthreads();
    for (int off = 128; off >= 1; off >>= 1) {
        if (t < off) sden[t] += sden[t + off];
        __syncthreads();
    }
    const float denom = fmaxf(sden[0], 1e-5f);
    if (t < HC) {
        float q = 0.f;
#pragma unroll
        for (int c = 0; c < NC; c++) q += sqg[c] * Wq[t * NC + c];
        sq[t] = q * 0.35355339059327373f / denom;
    }
    __syncthreads();

    const float q0 = sq[h*8+0], q1 = sq[h*8+1], q2 = sq[h*8+2], q3 = sq[h*8+3];
    const float q4 = sq[h*8+4], q5 = sq[h*8+5], q6 = sq[h*8+6], q7 = sq[h*8+7];

    float esum = 0.f;
    float cacc[8];
#pragma unroll
    for (int j = 0; j < 8; j++) cacc[j] = 0.f;

    for (int c0 = 0; c0 < NS; c0 += 256) {
        {
            const float4* kg = (const float4*)&g_k[((size_t)i * NS + c0) * 8];
            const float4* vg = (const float4*)&g_v[((size_t)i * NS + c0) * 8];
            const float4 ka = kg[t * 2], kb = kg[t * 2 + 1];
            const float4 va = vg[t * 2], vb = vg[t * 2 + 1];
            float* kd = &sk[t * KS9];
            float* vd = &sv[t * KS9];
            kd[0] = ka.x; kd[1] = ka.y; kd[2] = ka.z; kd[3] = ka.w;
            kd[4] = kb.x; kd[5] = kb.y; kd[6] = kb.z; kd[7] = kb.w;
            vd[0] = va.x; vd[1] = va.y; vd[2] = va.z; vd[3] = va.w;
            vd[4] = vb.x; vd[5] = vb.y; vd[6] = vb.z; vd[7] = vb.w;
            smk[t] = g_mcol[(size_t)i * NS + c0 + t];
        }
        __syncthreads();
#pragma unroll
        for (int j = 0; j < 8; j++) {
            const int s = lane + 32 * j;
            const float* kr = &sk[s * KS9];
            const float l = q0*kr[0] + q1*kr[1] + q2*kr[2] + q3*kr[3]
                          + q4*kr[4] + q5*kr[5] + q6*kr[6] + q7*kr[7];
            const float e = (smk[s] > 0.f) ? __expf(l) : 0.f;
            esum += e;
            const float* vr = &sv[s * KS9];
            cacc[0] += e * vr[0]; cacc[1] += e * vr[1];
            cacc[2] += e * vr[2]; cacc[3] += e * vr[3];
            cacc[4] += e * vr[4]; cacc[5] += e * vr[5];
            cacc[6] += e * vr[6]; cacc[7] += e * vr[7];
        }
        __syncthreads();
    }

#pragma unroll
    for (int d = 16; d; d >>= 1) esum += __shfl_xor_sync(0xffffffffu, esum, d);
#pragma unroll
    for (int j = 0; j < 8; j++)
#pragma unroll
        for (int d = 16; d; d >>= 1)
            cacc[j] += __shfl_xor_sync(0xffffffffu, cacc[j], d);

    if (lane == 0) {
        const float inv = 1.f / esum;
#pragma unroll
        for (int j = 0; j < 8; j++)
            g_ctx[i * HC + h * 8 + j] = cacc[j] * inv;
    }
}

// ==========================================================================
// Kernel 3: mma.sync bf16-split  LN -> GEMM1(Wg) -> sigmoid*ctx -> GEMM2(Wo).
// grid (NT, NI), block 128. COALESCED m staging through the weight smem area
// (weights copied after LN conversion).
// ==========================================================================
__global__ void __launch_bounds__(128) k_out(
    const float* __restrict__ m,
    const float* __restrict__ gamma, const float* __restrict__ beta,
    const float* __restrict__ bg, const float* __restrict__ bo,
    float* __restrict__ out) {
    extern __shared__ __align__(16) char smem[];
    const uint32_t sb = smem_u32(smem);
    const int t = threadIdx.x;
    const int warp = t >> 5, lane = t & 31;
    const int i  = blockIdx.y;
    const int s0 = blockIdx.x * TS;

    float* sctx = (float*)(smem + OFF_CTX);
    float* sbg  = (float*)(smem + OFF_BG);
    float* sbo  = (float*)(smem + OFF_BO);
    float* fst  = (float*)(smem + OFF_WGH);   // m staging (pre-weights)

    // phase A: coalesced stage of the m tile (16 threads per row, nL~4)
    for (int idx = t; idx < TS * NC / 4; idx += 128) {
        const int r = idx >> 4, c4 = (idx & 15) * 4;
        *(float4*)&fst[r * FST + c4] =
            *(const float4*)&m[((size_t)(s0 + r) * NI + i) * NC + c4];
    }
    if (t < 64) {
        sctx[t] = g_ctx[i * HC + t];
        sbg[t]  = bg[t];
        sbo[t]  = bo[t];
    }
    __syncthreads();

    // phase B: LN per row from smem, bf16 hi/lo into X tiles (packed STS.128)
    {
        const float* xr = &fst[t * FST];
        float x[NC];
        float s1 = 0.f, s2 = 0.f;
#pragma unroll
        for (int c4 = 0; c4 < NC; c4 += 4) {
            const float4 v = *(const float4*)&xr[c4];
            x[c4] = v.x; x[c4+1] = v.y; x[c4+2] = v.z; x[c4+3] = v.w;
            s1 += v.x + v.y + v.z + v.w;
            s2 += v.x*v.x + v.y*v.y + v.z*v.z + v.w*v.w;
        }
        const float mu   = s1 * (1.f / 64.f);
        const float var  = s2 * (1.f / 64.f) - mu * mu;
        const float rstd = rsqrtf(var + 1e-5f);
#pragma unroll
        for (int c = 0; c < NC; c++)
            x[c] = (x[c] - mu) * rstd * gamma[c] + beta[c];
#pragma unroll
        for (int c = 0; c < NC; c += 8) {
            uint32_t hw[4], lw[4];
#pragma unroll
            for (int j = 0; j < 4; j++) {
                const float x0 = x[c + 2*j], x1 = x[c + 2*j + 1];
                __nv_bfloat162 hp;
                hp.x = __float2bfloat16(x0);
                hp.y = __float2bfloat16(x1);
                hw[j] = *(uint32_t*)&hp;
                __nv_bfloat162 lp;
                lp.x = __float2bfloat16(x0 - __bfloat162float(hp.x));
                lp.y = __float2bfloat16(x1 - __bfloat162float(hp.y));
                lw[j] = *(uint32_t*)&lp;
            }
            *(uint4*)(smem + OFF_XHI + (t * XS + c) * 2) =
                make_uint4(hw[0], hw[1], hw[2], hw[3]);
            *(uint4*)(smem + OFF_XLO + (t * XS + c) * 2) =
                make_uint4(lw[0], lw[1], lw[2], lw[3]);
        }
    }
    __syncthreads();

    // phase C: copy bf16 weights into the (now free) staging area
    {
        uint4* dst = (uint4*)(smem + OFF_WGH);
        const uint4* s0p = (const uint4*)g_wgh;
        const uint4* s1p = (const uint4*)g_wgl;
        const uint4* s2p = (const uint4*)g_woh;
        const uint4* s3p = (const uint4*)g_wol;
        for (int idx = t; idx < 576; idx += 128) {
            dst[idx]        = s0p[idx];
            dst[576 + idx]  = s1p[idx];
            dst[1152 + idx] = s2p[idx];
            dst[1728 + idx] = s3p[idx];
        }
    }
    __syncthreads();

    float acc[2][8][4];
#pragma unroll
    for (int mt = 0; mt < 2; mt++)
#pragma unroll
        for (int nt = 0; nt < 8; nt++)
#pragma unroll
            for (int p = 0; p < 4; p++) acc[mt][nt][p] = 0.f;

    // ---------------- GEMM1: G = X @ Wg^T ----------------
    gemm_bf16_split(sb + OFF_XHI, sb + OFF_XLO, sb + OFF_WGH, sb + OFF_WGL,
                    warp, lane, acc);
    __syncthreads();   // all ldmatrix reads of X done before overwrite

    // gate: o = ctx * sigmoid(d + bg); write O hi/lo back into X tiles
    {
        const int tr = lane >> 2;
        const int tc = (lane & 3) * 2;
#pragma unroll
        for (int mt = 0; mt < 2; mt++) {
#pragma unroll
            for (int nt = 0; nt < 8; nt++) {
                const int c0 = nt * 8 + tc;
                const float cx0 = sctx[c0], cx1 = sctx[c0 + 1];
                const float b0 = sbg[c0],  b1 = sbg[c0 + 1];
#pragma unroll
                for (int half = 0; half < 2; half++) {
                    const int r = warp * 32 + mt * 16 + tr + half * 8;
                    const float d0 = acc[mt][nt][half * 2]     + b0;
                    const float d1 = acc[mt][nt][half * 2 + 1] + b1;
                    const float o0 = cx0 * __fdividef(1.f, 1.f + __expf(-d0));
                    const float o1 = cx1 * __fdividef(1.f, 1.f + __expf(-d1));
                    __nv_bfloat162 hp;
                    hp.x = __float2bfloat16(o0);
                    hp.y = __float2bfloat16(o1);
                    *(__nv_bfloat162*)(smem + OFF_XHI + (r * XS + c0) * 2) = hp;
                    __nv_bfloat162 lp;
                    lp.x = __float2bfloat16(o0 - __bfloat162float(hp.x));
                    lp.y = __float2bfloat16(o1 - __bfloat162float(hp.y));
                    *(__nv_bfloat162*)(smem + OFF_XLO + (r * XS + c0) * 2) = lp;
                }
            }
        }
    }
    __syncthreads();

#pragma unroll
    for (int mt = 0; mt < 2; mt++)
#pragma unroll
        for (int nt = 0; nt < 8; nt++)
#pragma unroll
            for (int p = 0; p < 4; p++) acc[mt][nt][p] = 0.f;

    // ---------------- GEMM2: out = O @ Wo^T + bo ----------------
    gemm_bf16_split(sb + OFF_XHI, sb + OFF_XLO, sb + OFF_WOH, sb + OFF_WOL,
                    warp, lane, acc);

    // epilogue: + bo, store float2 per fragment element pair
    {
        const int tr = lane >> 2;
        const int tc = (lane & 3) * 2;
#pragma unroll
        for (int mt = 0; mt < 2; mt++) {
#pragma unroll
            for (int nt = 0; nt < 8; nt++) {
                const int c0 = nt * 8 + tc;
                const float b0 = sbo[c0], b1 = sbo[c0 + 1];
#pragma unroll
                for (int half = 0; half < 2; half++) {
                    const int r = warp * 32 + mt * 16 + tr + half * 8;
                    float2 v;
                    v.x = acc[mt][nt][half * 2]     + b0;
                    v.y = acc[mt][nt][half * 2 + 1] + b1;
                    *(float2*)&out[((size_t)(s0 + r) * NI + i) * NC + c0] = v;
                }
            }
        }
    }
}

// ==========================================================================
extern "C" void kernel_launch(void* const* d_in, const int* in_sizes, int n_in,
                              void* d_out, int out_size) {
    const float* m     = (const float*)d_in[0];
    const float* mask  = (const float*)d_in[1];
    const float* gamma = (const float*)d_in[2];
    const float* beta  = (const float*)d_in[3];
    const float* Wq    = (const float*)d_in[4];
    const float* Wk    = (const float*)d_in[5];
    const float* Wv    = (const float*)d_in[6];
    const float* Wg    = (const float*)d_in[7];
    const float* bg    = (const float*)d_in[8];
    const float* Wo    = (const float*)d_in[9];
    const float* bo    = (const float*)d_in[10];
    float* out = (float*)d_out;

    cudaFuncSetAttribute(k_out, cudaFuncAttributeMaxDynamicSharedMemorySize,
                         SMEM_TOTAL_OUT);

    dim3 g1(NT, NI);
    k_pass1<<<g1, TS>>>(m, mask, gamma, beta, Wk, Wv, Wg, Wo);
    k_attn<<<NI, 256>>>(Wq);
    dim3 g4(NT, NI);
    k_out<<<g4, 128, SMEM_TOTAL_OUT>>>(m, gamma, beta, bg, bo, out);
}

// round 16
// speedup vs baseline: 1.2196x; 1.2196x over previous
#include <cuda_runtime.h>
#include <cuda_bf16.h>
#include <cstdint>

#define NS   2048
#define NI   384
#define NC   64
#define NH   8
#define HC   64
#define TS   128          // rows per tile (= GEMM M per block)
#define NT   (NS / TS)    // 16 tiles
#define TP   65           // k_pass1 smem tile stride (scalar access only)
#define XS   72           // bf16 tile row stride (elements) — ldmatrix conflict-free
#define KS9  9            // k_attn smem row stride (floats) — conflict-free

// k_out dynamic smem offsets (bytes) — both weight pairs resident (R11 layout)
#define OFF_CTX  0
#define OFF_BG   256
#define OFF_BO   512
#define OFF_XHI  1024
#define OFF_XLO  (OFF_XHI + TS * XS * 2)        // 19456
#define OFF_WGH  (OFF_XLO + TS * XS * 2)        // 37888
#define OFF_WGL  (OFF_WGH + NC * XS * 2)        // 47104
#define OFF_WOH  (OFF_WGL + NC * XS * 2)        // 56320
#define OFF_WOL  (OFF_WOH + NC * XS * 2)        // 65536
#define SMEM_TOTAL_OUT (OFF_WOL + NC * XS * 2)  // 74752

// ---------------- scratch (device globals; no allocation) ----------------
__device__ __align__(16) float g_k[(size_t)NI * NS * 8];   // [i][s][ch]
__device__ __align__(16) float g_v[(size_t)NI * NS * 8];   // [i][s][ch]
__device__ float g_mcol[(size_t)NI * NS];                  // mask, column-major
__device__ float g_qpart[NT * NI * NC];                    // [tile][i][c]
__device__ float g_ctx[NI * HC];                           // [i][h*8+ch]
// bf16 hi/lo weights, [n][k] K-major, row stride XS
__device__ __align__(16) __nv_bfloat16 g_wgh[NC * XS];
__device__ __align__(16) __nv_bfloat16 g_wgl[NC * XS];
__device__ __align__(16) __nv_bfloat16 g_woh[NC * XS];
__device__ __align__(16) __nv_bfloat16 g_wol[NC * XS];

// ---------------- packed fp32x2 helpers (FFMA2 path, k_pass1) -------------
__device__ __forceinline__ unsigned long long pk2(float x, float y) {
    unsigned long long r;
    asm("mov.b64 %0, {%1, %2};" : "=l"(r) : "f"(x), "f"(y));
    return r;
}
__device__ __forceinline__ void upk2(unsigned long long v, float& x, float& y) {
    asm("mov.b64 {%0, %1}, %2;" : "=f"(x), "=f"(y) : "l"(v));
}
__device__ __forceinline__ unsigned long long f2fma(unsigned long long a,
                                                    unsigned long long b,
                                                    unsigned long long c) {
    unsigned long long d;
    asm("fma.rn.f32x2 %0, %1, %2, %3;" : "=l"(d) : "l"(a), "l"(b), "l"(c));
    return d;
}

// ---------------- mma.sync / ldmatrix helpers (base ISA, sm_80+) ----------
__device__ __forceinline__ uint32_t smem_u32(const void* p) {
    uint32_t a;
    asm("{ .reg .u64 t; cvta.to.shared.u64 t, %1; cvt.u32.u64 %0, t; }"
        : "=r"(a) : "l"(p));
    return a;
}
__device__ __forceinline__ void ldmx4(uint32_t* r, uint32_t addr) {
    asm volatile("ldmatrix.sync.aligned.m8n8.x4.shared.b16 {%0,%1,%2,%3}, [%4];"
                 : "=r"(r[0]), "=r"(r[1]), "=r"(r[2]), "=r"(r[3]) : "r"(addr));
}
__device__ __forceinline__ void mma16816(float* d, const uint32_t* a,
                                         const uint32_t* b) {
    asm volatile(
        "mma.sync.aligned.m16n8k16.row.col.f32.bf16.bf16.f32 "
        "{%0,%1,%2,%3}, {%4,%5,%6,%7}, {%8,%9}, {%0,%1,%2,%3};"
        : "+f"(d[0]), "+f"(d[1]), "+f"(d[2]), "+f"(d[3])
        : "r"(a[0]), "r"(a[1]), "r"(a[2]), "r"(a[3]), "r"(b[0]), "r"(b[1]));
}

// 3-pass bf16-split GEMM: acc += Xh*Wh + Xh*Wl + Xl*Wh  (M=128,N=64,K=64).
// B fragments loaded as ldmatrix.x4 PAIRS (two n-tiles per instruction):
// lanes 0-15 address pair-member 0, lanes 16-31 pair-member 1.
__device__ __forceinline__ void gemm_bf16_split(
    uint32_t xh, uint32_t xl, uint32_t wh, uint32_t wl,
    int warp, int lane, float acc[2][8][4]) {
    const int arow = ((lane >> 3) & 1) * 8 + (lane & 7);
    const int acol = (lane >> 4) * 8;
    const int brow = lane & 7;
    const int bcol = ((lane >> 3) & 1) * 8;
    const int bsel = lane >> 4;        // which n-tile of the pair
#pragma unroll
    for (int ks = 0; ks < 4; ks++) {
        uint32_t ah[2][4], al[2][4];
#pragma unroll
        for (int mt = 0; mt < 2; mt++) {
            const uint32_t aoff =
                (uint32_t)(((warp * 32 + mt * 16 + arow) * XS + ks * 16 + acol) * 2);
            ldmx4(ah[mt], xh + aoff);
            ldmx4(al[mt], xl + aoff);
        }
#pragma unroll
        for (int np = 0; np < 4; np++) {   // pairs of n-tiles
            const uint32_t boff =
                (uint32_t)((((np * 2 + bsel) * 8 + brow) * XS + ks * 16 + bcol) * 2);
            uint32_t bh[4], bl[4];
            ldmx4(bh, wh + boff);
            ldmx4(bl, wl + boff);
#pragma unroll
            for (int mt = 0; mt < 2; mt++) {
                mma16816(acc[mt][np * 2],     ah[mt], bh);
                mma16816(acc[mt][np * 2],     ah[mt], bl);
                mma16816(acc[mt][np * 2],     al[mt], bh);
                mma16816(acc[mt][np * 2 + 1], ah[mt], bh + 2);
                mma16816(acc[mt][np * 2 + 1], ah[mt], bl + 2);
                mma16816(acc[mt][np * 2 + 1], al[mt], bh + 2);
            }
        }
    }
}

// ==========================================================================
// Kernel 1: LN + k/v projection (FFMA2) + q_global partials + mask repack.
// Block (0,0) additionally performs the one-time bf16 weight prep.
// grid (NT, NI), block TS=128. One thread = one s-row. (R11 proven config.)
// ==========================================================================
__global__ void __launch_bounds__(TS) k_pass1(
    const float* __restrict__ m, const float* __restrict__ mask,
    const float* __restrict__ gamma, const float* __restrict__ beta,
    const float* __restrict__ Wk, const float* __restrict__ Wv,
    const float* __restrict__ Wg, const float* __restrict__ Wo) {
    __shared__ float tile[TS * TP];
    __shared__ __align__(16) float sWT[NC * 16];  // [c][0..7]=Wk, [c][8..15]=Wv
    __shared__ float sg[NC], sb[NC];

    const int i  = blockIdx.y;
    const int s0 = blockIdx.x * TS;
    const int t  = threadIdx.x;

    if (blockIdx.x == 0 && blockIdx.y == 0) {
        for (int idx = t; idx < NC * NC; idx += TS) {
            const int n = idx >> 6, k = idx & 63;
            const int dst = n * XS + k;
            const float wg = Wg[idx];
            const __nv_bfloat16 gh = __float2bfloat16(wg);
            g_wgh[dst] = gh;
            g_wgl[dst] = __float2bfloat16(wg - __bfloat162float(gh));
            const float wo = Wo[idx];
            const __nv_bfloat16 oh = __float2bfloat16(wo);
            g_woh[dst] = oh;
            g_wol[dst] = __float2bfloat16(wo - __bfloat162float(oh));
        }
    }

    for (int idx = t; idx < 8 * NC; idx += TS) {
        const int j = idx >> 6, c = idx & 63;
        sWT[c * 16 + j]     = Wk[idx];
        sWT[c * 16 + 8 + j] = Wv[idx];
    }
    if (t < NC) { sg[t] = gamma[t]; sb[t] = beta[t]; }
    for (int idx = t; idx < TS * NC / 4; idx += TS) {
        const int r = idx >> 4, c4 = (idx & 15) * 4;
        const float4 v = *(const float4*)&m[((size_t)(s0 + r) * NI + i) * NC + c4];
        tile[r * TP + c4 + 0] = v.x;
        tile[r * TP + c4 + 1] = v.y;
        tile[r * TP + c4 + 2] = v.z;
        tile[r * TP + c4 + 3] = v.w;
    }
    __syncthreads();

    float s1 = 0.f, s2 = 0.f;
#pragma unroll
    for (int c = 0; c < NC; c++) {
        const float v = tile[t * TP + c];
        s1 += v; s2 += v * v;
    }
    const float mu   = s1 * (1.f / 64.f);
    const float var  = s2 * (1.f / 64.f) - mu * mu;
    const float rstd = rsqrtf(var + 1e-5f);
    const float maskv = mask[(size_t)(s0 + t) * NI + i];
    g_mcol[(size_t)i * NS + s0 + t] = maskv;

    unsigned long long ka2[4], va2[4];
#pragma unroll
    for (int j = 0; j < 4; j++) { ka2[j] = 0ull; va2[j] = 0ull; }

#pragma unroll
    for (int c = 0; c < NC; c++) {
        const float mn = (tile[t * TP + c] - mu) * rstd * sg[c] + sb[c];
        tile[t * TP + c] = mn * maskv;
        const unsigned long long mp = pk2(mn, mn);
        const ulonglong2 wk  = *(const ulonglong2*)&sWT[c * 16];
        const ulonglong2 wk1 = *(const ulonglong2*)&sWT[c * 16 + 4];
        const ulonglong2 wv  = *(const ulonglong2*)&sWT[c * 16 + 8];
        const ulonglong2 wv1 = *(const ulonglong2*)&sWT[c * 16 + 12];
        ka2[0] = f2fma(mp, wk.x,  ka2[0]);
        ka2[1] = f2fma(mp, wk.y,  ka2[1]);
        ka2[2] = f2fma(mp, wk1.x, ka2[2]);
        ka2[3] = f2fma(mp, wk1.y, ka2[3]);
        va2[0] = f2fma(mp, wv.x,  va2[0]);
        va2[1] = f2fma(mp, wv.y,  va2[1]);
        va2[2] = f2fma(mp, wv1.x, va2[2]);
        va2[3] = f2fma(mp, wv1.y, va2[3]);
    }

    float kr[8], vr[8];
#pragma unroll
    for (int j = 0; j < 4; j++) {
        upk2(ka2[j], kr[2 * j], kr[2 * j + 1]);
        upk2(va2[j], vr[2 * j], vr[2 * j + 1]);
    }
    float4* kp = (float4*)&g_k[((size_t)i * NS + s0 + t) * 8];
    float4* vp = (float4*)&g_v[((size_t)i * NS + s0 + t) * 8];
    kp[0] = make_float4(kr[0], kr[1], kr[2], kr[3]);
    kp[1] = make_float4(kr[4], kr[5], kr[6], kr[7]);
    vp[0] = make_float4(vr[0], vr[1], vr[2], vr[3]);
    vp[1] = make_float4(vr[4], vr[5], vr[6], vr[7]);
    __syncthreads();

    if (t < NC) {
        float a0 = 0.f, a1 = 0.f, a2 = 0.f, a3 = 0.f;
        for (int r = 0; r < TS; r += 4) {
            a0 += tile[(r + 0) * TP + t];
            a1 += tile[(r + 1) * TP + t];
            a2 += tile[(r + 2) * TP + t];
            a3 += tile[(r + 3) * TP + t];
        }
        g_qpart[((size_t)blockIdx.x * NI + i) * NC + t] = (a0 + a1) + (a2 + a3);
    }
}

// ==========================================================================
// Kernel 2: q projection (merged) + DOUBLE-BUFFERED smem-staged warp-per-head
// attention. grid NI, block 256 (8 warps = 8 heads). One-pass softmax.
// ==========================================================================
__global__ void __launch_bounds__(256) k_attn(const float* __restrict__ Wq) {
    __shared__ float sq[HC];
    __shared__ float sqg[NC];
    __shared__ float sden[256];
    __shared__ float sk[2][256 * KS9];
    __shared__ float sv[2][256 * KS9];
    __shared__ float smk[2][256];

    const int i = blockIdx.x;
    const int t = threadIdx.x;
    const int h = t >> 5, lane = t & 31;

    // ---- q projection prologue (merged k_q) ----
    float dsum = 0.f;
    for (int s = t; s < NS; s += 256) dsum += g_mcol[(size_t)i * NS + s];
    sden[t] = dsum;
    if (t < NC) {
        float acc = 0.f;
        for (int tt = 0; tt < NT; tt++)
            acc += g_qpart[((size_t)tt * NI + i) * NC + t];
        sqg[t] = acc;
    }
    __syncthreads();
    for (int off = 128; off >= 1; off >>= 1) {
        if (t < off) sden[t] += sden[t + off];
        __syncthreads();
    }
    const float denom = fmaxf(sden[0], 1e-5f);
    if (t < HC) {
        float q = 0.f;
#pragma unroll
        for (int c = 0; c < NC; c++) q += sqg[c] * Wq[t * NC + c];
        sq[t] = q * 0.35355339059327373f / denom;
    }
    __syncthreads();

    const float q0 = sq[h*8+0], q1 = sq[h*8+1], q2 = sq[h*8+2], q3 = sq[h*8+3];
    const float q4 = sq[h*8+4], q5 = sq[h*8+5], q6 = sq[h*8+6], q7 = sq[h*8+7];

    float esum = 0.f;
    float cacc[8];
#pragma unroll
    for (int j = 0; j < 8; j++) cacc[j] = 0.f;

    // prologue: load + store chunk 0
    float4 pka, pkb, pva, pvb;
    float pmk;
    {
        const float4* kg = (const float4*)&g_k[(size_t)i * NS * 8];
        const float4* vg = (const float4*)&g_v[(size_t)i * NS * 8];
        pka = kg[t * 2]; pkb = kg[t * 2 + 1];
        pva = vg[t * 2]; pvb = vg[t * 2 + 1];
        pmk = g_mcol[(size_t)i * NS + t];
        float* kd = &sk[0][t * KS9];
        float* vd = &sv[0][t * KS9];
        kd[0] = pka.x; kd[1] = pka.y; kd[2] = pka.z; kd[3] = pka.w;
        kd[4] = pkb.x; kd[5] = pkb.y; kd[6] = pkb.z; kd[7] = pkb.w;
        vd[0] = pva.x; vd[1] = pva.y; vd[2] = pva.z; vd[3] = pva.w;
        vd[4] = pvb.x; vd[5] = pvb.y; vd[6] = pvb.z; vd[7] = pvb.w;
        smk[0][t] = pmk;
    }

    const int NCHUNK = NS / 256;   // 8
#pragma unroll 1
    for (int j = 0; j < NCHUNK; j++) {
        // issue next chunk's loads BEFORE the barrier (latency overlaps)
        if (j + 1 < NCHUNK) {
            const int c0 = (j + 1) * 256;
            const float4* kg = (const float4*)&g_k[((size_t)i * NS + c0) * 8];
            const float4* vg = (const float4*)&g_v[((size_t)i * NS + c0) * 8];
            pka = kg[t * 2]; pkb = kg[t * 2 + 1];
            pva = vg[t * 2]; pvb = vg[t * 2 + 1];
            pmk = g_mcol[(size_t)i * NS + c0 + t];
        }
        __syncthreads();   // buf[j&1] visible; prior reads of buf[(j+1)&1] done

        const int b = j & 1;
#pragma unroll
        for (int u = 0; u < 8; u++) {
            const int s = lane + 32 * u;
            const float* kr = &sk[b][s * KS9];
            const float l = q0*kr[0] + q1*kr[1] + q2*kr[2] + q3*kr[3]
                          + q4*kr[4] + q5*kr[5] + q6*kr[6] + q7*kr[7];
            const float e = (smk[b][s] > 0.f) ? __expf(l) : 0.f;
            esum += e;
            const float* vr = &sv[b][s * KS9];
            cacc[0] += e * vr[0]; cacc[1] += e * vr[1];
            cacc[2] += e * vr[2]; cacc[3] += e * vr[3];
            cacc[4] += e * vr[4]; cacc[5] += e * vr[5];
            cacc[6] += e * vr[6]; cacc[7] += e * vr[7];
        }

        if (j + 1 < NCHUNK) {
            const int nb = (j + 1) & 1;
            float* kd = &sk[nb][t * KS9];
            float* vd = &sv[nb][t * KS9];
            kd[0] = pka.x; kd[1] = pka.y; kd[2] = pka.z; kd[3] = pka.w;
            kd[4] = pkb.x; kd[5] = pkb.y; kd[6] = pkb.z; kd[7] = pkb.w;
            vd[0] = pva.x; vd[1] = pva.y; vd[2] = pva.z; vd[3] = pva.w;
            vd[4] = pvb.x; vd[5] = pvb.y; vd[6] = pvb.z; vd[7] = pvb.w;
            smk[nb][t] = pmk;
        }
    }

#pragma unroll
    for (int d = 16; d; d >>= 1) esum += __shfl_xor_sync(0xffffffffu, esum, d);
#pragma unroll
    for (int j = 0; j < 8; j++)
#pragma unroll
        for (int d = 16; d; d >>= 1)
            cacc[j] += __shfl_xor_sync(0xffffffffu, cacc[j], d);

    if (lane == 0) {
        const float inv = 1.f / esum;
#pragma unroll
        for (int j = 0; j < 8; j++)
            g_ctx[i * HC + h * 8 + j] = cacc[j] * inv;
    }
}

// ==========================================================================
// Kernel 3: mma.sync bf16-split  LN -> GEMM1(Wg) -> sigmoid*ctx -> GEMM2(Wo).
// grid (NT, NI), block 128. Both weight pairs resident (R11 config),
// B fragments via paired ldmatrix.x4.
// ==========================================================================
__global__ void __launch_bounds__(128) k_out(
    const float* __restrict__ m,
    const float* __restrict__ gamma, const float* __restrict__ beta,
    const float* __restrict__ bg, const float* __restrict__ bo,
    float* __restrict__ out) {
    extern __shared__ __align__(16) char smem[];
    const uint32_t sb = smem_u32(smem);
    const int t = threadIdx.x;
    const int warp = t >> 5, lane = t & 31;
    const int i  = blockIdx.y;
    const int s0 = blockIdx.x * TS;

    float* sctx = (float*)(smem + OFF_CTX);
    float* sbg  = (float*)(smem + OFF_BG);
    float* sbo  = (float*)(smem + OFF_BO);

    // copy bf16 weights (4 tiles x 9216B = 2304 uint4)
    {
        uint4* dst = (uint4*)(smem + OFF_WGH);
        const uint4* s0p = (const uint4*)g_wgh;
        const uint4* s1p = (const uint4*)g_wgl;
        const uint4* s2p = (const uint4*)g_woh;
        const uint4* s3p = (const uint4*)g_wol;
        for (int idx = t; idx < 576; idx += 128) {
            dst[idx]        = s0p[idx];
            dst[576 + idx]  = s1p[idx];
            dst[1152 + idx] = s2p[idx];
            dst[1728 + idx] = s3p[idx];
        }
    }
    if (t < 64) {
        sctx[t] = g_ctx[i * HC + t];
        sbg[t]  = bg[t];
        sbo[t]  = bo[t];
    }

    // LN on own row, bf16 hi/lo into X tiles — packed STS.128 (conflict-free)
    {
        const float* mr = &m[((size_t)(s0 + t) * NI + i) * NC];
        float x[NC];
        float s1 = 0.f, s2 = 0.f;
#pragma unroll
        for (int c4 = 0; c4 < NC; c4 += 4) {
            const float4 v = *(const float4*)&mr[c4];
            x[c4] = v.x; x[c4+1] = v.y; x[c4+2] = v.z; x[c4+3] = v.w;
            s1 += v.x + v.y + v.z + v.w;
            s2 += v.x*v.x + v.y*v.y + v.z*v.z + v.w*v.w;
        }
        const float mu   = s1 * (1.f / 64.f);
        const float var  = s2 * (1.f / 64.f) - mu * mu;
        const float rstd = rsqrtf(var + 1e-5f);
#pragma unroll
        for (int c = 0; c < NC; c++)
            x[c] = (x[c] - mu) * rstd * gamma[c] + beta[c];
#pragma unroll
        for (int c = 0; c < NC; c += 8) {
            uint32_t hw[4], lw[4];
#pragma unroll
            for (int j = 0; j < 4; j++) {
                const float x0 = x[c + 2*j], x1 = x[c + 2*j + 1];
                __nv_bfloat162 hp;
                hp.x = __float2bfloat16(x0);
                hp.y = __float2bfloat16(x1);
                hw[j] = *(uint32_t*)&hp;
                __nv_bfloat162 lp;
                lp.x = __float2bfloat16(x0 - __bfloat162float(hp.x));
                lp.y = __float2bfloat16(x1 - __bfloat162float(hp.y));
                lw[j] = *(uint32_t*)&lp;
            }
            *(uint4*)(smem + OFF_XHI + (t * XS + c) * 2) =
                make_uint4(hw[0], hw[1], hw[2], hw[3]);
            *(uint4*)(smem + OFF_XLO + (t * XS + c) * 2) =
                make_uint4(lw[0], lw[1], lw[2], lw[3]);
        }
    }
    __syncthreads();

    float acc[2][8][4];
#pragma unroll
    for (int mt = 0; mt < 2; mt++)
#pragma unroll
        for (int nt = 0; nt < 8; nt++)
#pragma unroll
            for (int p = 0; p < 4; p++) acc[mt][nt][p] = 0.f;

    // ---------------- GEMM1: G = X @ Wg^T ----------------
    gemm_bf16_split(sb + OFF_XHI, sb + OFF_XLO, sb + OFF_WGH, sb + OFF_WGL,
                    warp, lane, acc);
    __syncthreads();   // all ldmatrix reads of X done before overwrite

    // gate: o = ctx * sigmoid(d + bg); write O hi/lo back into X tiles
    {
        const int tr = lane >> 2;
        const int tc = (lane & 3) * 2;
#pragma unroll
        for (int mt = 0; mt < 2; mt++) {
#pragma unroll
            for (int nt = 0; nt < 8; nt++) {
                const int c0 = nt * 8 + tc;
                const float cx0 = sctx[c0], cx1 = sctx[c0 + 1];
                const float b0 = sbg[c0],  b1 = sbg[c0 + 1];
#pragma unroll
                for (int half = 0; half < 2; half++) {
                    const int r = warp * 32 + mt * 16 + tr + half * 8;
                    const float d0 = acc[mt][nt][half * 2]     + b0;
                    const float d1 = acc[mt][nt][half * 2 + 1] + b1;
                    const float o0 = cx0 * __fdividef(1.f, 1.f + __expf(-d0));
                    const float o1 = cx1 * __fdividef(1.f, 1.f + __expf(-d1));
                    __nv_bfloat162 hp;
                    hp.x = __float2bfloat16(o0);
                    hp.y = __float2bfloat16(o1);
                    *(__nv_bfloat162*)(smem + OFF_XHI + (r * XS + c0) * 2) = hp;
                    __nv_bfloat162 lp;
                    lp.x = __float2bfloat16(o0 - __bfloat162float(hp.x));
                    lp.y = __float2bfloat16(o1 - __bfloat162float(hp.y));
                    *(__nv_bfloat162*)(smem + OFF_XLO + (r * XS + c0) * 2) = lp;
                }
            }
        }
    }
    __syncthreads();

#pragma unroll
    for (int mt = 0; mt < 2; mt++)
#pragma unroll
        for (int nt = 0; nt < 8; nt++)
#pragma unroll
            for (int p = 0; p < 4; p++) acc[mt][nt][p] = 0.f;

    // ---------------- GEMM2: out = O @ Wo^T + bo ----------------
    gemm_bf16_split(sb + OFF_XHI, sb + OFF_XLO, sb + OFF_WOH, sb + OFF_WOL,
                    warp, lane, acc);

    // epilogue: + bo, store float2 per fragment element pair
    {
        const int tr = lane >> 2;
        const int tc = (lane & 3) * 2;
#pragma unroll
        for (int mt = 0; mt < 2; mt++) {
#pragma unroll
            for (int nt = 0; nt < 8; nt++) {
                const int c0 = nt * 8 + tc;
                const float b0 = sbo[c0], b1 = sbo[c0 + 1];
#pragma unroll
                for (int half = 0; half < 2; half++) {
                    const int r = warp * 32 + mt * 16 + tr + half * 8;
                    float2 v;
                    v.x = acc[mt][nt][half * 2]     + b0;
                    v.y = acc[mt][nt][half * 2 + 1] + b1;
                    *(float2*)&out[((size_t)(s0 + r) * NI + i) * NC + c0] = v;
                }
            }
        }
    }
}

// ==========================================================================
extern "C" void kernel_launch(void* const* d_in, const int* in_sizes, int n_in,
                              void* d_out, int out_size) {
    const float* m     = (const float*)d_in[0];
    const float* mask  = (const float*)d_in[1];
    const float* gamma = (const float*)d_in[2];
    const float* beta  = (const float*)d_in[3];
    const float* Wq    = (const float*)d_in[4];
    const float* Wk    = (const float*)d_in[5];
    const float* Wv    = (const float*)d_in[6];
    const float* Wg    = (const float*)d_in[7];
    const float* bg    = (const float*)d_in[8];
    const float* Wo    = (const float*)d_in[9];
    const float* bo    = (const float*)d_in[10];
    float* out = (float*)d_out;

    cudaFuncSetAttribute(k_out, cudaFuncAttributeMaxDynamicSharedMemorySize,
                         SMEM_TOTAL_OUT);

    dim3 g1(NT, NI);
    k_pass1<<<g1, TS>>>(m, mask, gamma, beta, Wk, Wv, Wg, Wo);
    k_attn<<<NI, 256>>>(Wq);
    dim3 g4(NT, NI);
    k_out<<<g4, 128, SMEM_TOTAL_OUT>>>(m, gamma, beta, bg, bo, out);
}

// round 17
// speedup vs baseline: 1.2874x; 1.0557x over previous
#include <cuda_runtime.h>
#include <cuda_bf16.h>
#include <cstdint>

#define NS   2048
#define NI   384
#define NC   64
#define NH   8
#define HC   64
#define TS   128          // rows per tile (= GEMM M per block)
#define NT   (NS / TS)    // 16 tiles
#define TP   65           // k_pass1 smem tile stride (scalar access only)
#define XS   72           // bf16 tile row stride (elements) — ldmatrix conflict-free
#define KS9  9            // k_attn smem row stride (floats) — conflict-free

// k_out dynamic smem offsets (bytes) — both weight pairs resident (R11 layout)
#define OFF_CTX  0
#define OFF_BG   256
#define OFF_BO   512
#define OFF_XHI  1024
#define OFF_XLO  (OFF_XHI + TS * XS * 2)        // 19456
#define OFF_WGH  (OFF_XLO + TS * XS * 2)        // 37888
#define OFF_WGL  (OFF_WGH + NC * XS * 2)        // 47104
#define OFF_WOH  (OFF_WGL + NC * XS * 2)        // 56320
#define OFF_WOL  (OFF_WOH + NC * XS * 2)        // 65536
#define SMEM_TOTAL_OUT (OFF_WOL + NC * XS * 2)  // 74752

// ---------------- scratch (device globals; no allocation) ----------------
__device__ __align__(16) float g_k[(size_t)NI * NS * 8];   // [i][s][ch]
__device__ __align__(16) float g_v[(size_t)NI * NS * 8];   // [i][s][ch]
__device__ float g_mcol[(size_t)NI * NS];                  // mask, column-major
__device__ float g_qpart[NT * NI * NC];                    // [tile][i][c]
__device__ float g_ctx[NI * HC];                           // [i][h*8+ch]
// bf16 hi/lo weights, [n][k] K-major, row stride XS
__device__ __align__(16) __nv_bfloat16 g_wgh[NC * XS];
__device__ __align__(16) __nv_bfloat16 g_wgl[NC * XS];
__device__ __align__(16) __nv_bfloat16 g_woh[NC * XS];
__device__ __align__(16) __nv_bfloat16 g_wol[NC * XS];

// ---------------- packed fp32x2 helpers (FFMA2 path, k_pass1) -------------
__device__ __forceinline__ unsigned long long pk2(float x, float y) {
    unsigned long long r;
    asm("mov.b64 %0, {%1, %2};" : "=l"(r) : "f"(x), "f"(y));
    return r;
}
__device__ __forceinline__ void upk2(unsigned long long v, float& x, float& y) {
    asm("mov.b64 {%0, %1}, %2;" : "=f"(x), "=f"(y) : "l"(v));
}
__device__ __forceinline__ unsigned long long f2fma(unsigned long long a,
                                                    unsigned long long b,
                                                    unsigned long long c) {
    unsigned long long d;
    asm("fma.rn.f32x2 %0, %1, %2, %3;" : "=l"(d) : "l"(a), "l"(b), "l"(c));
    return d;
}

// ---------------- mma.sync / ldmatrix helpers (base ISA, sm_80+) ----------
__device__ __forceinline__ uint32_t smem_u32(const void* p) {
    uint32_t a;
    asm("{ .reg .u64 t; cvta.to.shared.u64 t, %1; cvt.u32.u64 %0, t; }"
        : "=r"(a) : "l"(p));
    return a;
}
__device__ __forceinline__ void ldmx4(uint32_t* r, uint32_t addr) {
    asm volatile("ldmatrix.sync.aligned.m8n8.x4.shared.b16 {%0,%1,%2,%3}, [%4];"
                 : "=r"(r[0]), "=r"(r[1]), "=r"(r[2]), "=r"(r[3]) : "r"(addr));
}
__device__ __forceinline__ void mma16816(float* d, const uint32_t* a,
                                         const uint32_t* b) {
    asm volatile(
        "mma.sync.aligned.m16n8k16.row.col.f32.bf16.bf16.f32 "
        "{%0,%1,%2,%3}, {%4,%5,%6,%7}, {%8,%9}, {%0,%1,%2,%3};"
        : "+f"(d[0]), "+f"(d[1]), "+f"(d[2]), "+f"(d[3])
        : "r"(a[0]), "r"(a[1]), "r"(a[2]), "r"(a[3]), "r"(b[0]), "r"(b[1]));
}

// 3-pass bf16-split GEMM: acc += Xh*Wh + Xh*Wl + Xl*Wh  (M=128,N=64,K=64).
// B fragments loaded as ldmatrix.x4 PAIRS (two n-tiles per instruction).
__device__ __forceinline__ void gemm_bf16_split(
    uint32_t xh, uint32_t xl, uint32_t wh, uint32_t wl,
    int warp, int lane, float acc[2][8][4]) {
    const int arow = ((lane >> 3) & 1) * 8 + (lane & 7);
    const int acol = (lane >> 4) * 8;
    const int brow = lane & 7;
    const int bcol = ((lane >> 3) & 1) * 8;
    const int bsel = lane >> 4;        // which n-tile of the pair
#pragma unroll
    for (int ks = 0; ks < 4; ks++) {
        uint32_t ah[2][4], al[2][4];
#pragma unroll
        for (int mt = 0; mt < 2; mt++) {
            const uint32_t aoff =
                (uint32_t)(((warp * 32 + mt * 16 + arow) * XS + ks * 16 + acol) * 2);
            ldmx4(ah[mt], xh + aoff);
            ldmx4(al[mt], xl + aoff);
        }
#pragma unroll
        for (int np = 0; np < 4; np++) {   // pairs of n-tiles
            const uint32_t boff =
                (uint32_t)((((np * 2 + bsel) * 8 + brow) * XS + ks * 16 + bcol) * 2);
            uint32_t bh[4], bl[4];
            ldmx4(bh, wh + boff);
            ldmx4(bl, wl + boff);
#pragma unroll
            for (int mt = 0; mt < 2; mt++) {
                mma16816(acc[mt][np * 2],     ah[mt], bh);
                mma16816(acc[mt][np * 2],     ah[mt], bl);
                mma16816(acc[mt][np * 2],     al[mt], bh);
                mma16816(acc[mt][np * 2 + 1], ah[mt], bh + 2);
                mma16816(acc[mt][np * 2 + 1], ah[mt], bl + 2);
                mma16816(acc[mt][np * 2 + 1], al[mt], bh + 2);
            }
        }
    }
}

// ==========================================================================
// Kernel 1: LN + k/v projection (FFMA2) + q_global partials + mask repack.
// Block (0,0) additionally performs the one-time bf16 weight prep.
// grid (NT, NI), block TS=128. One thread = one s-row.
// __launch_bounds__(128, 5): force regs <= 102 -> 5 blocks/SM (was 4).
// ==========================================================================
__global__ void __launch_bounds__(TS, 5) k_pass1(
    const float* __restrict__ m, const float* __restrict__ mask,
    const float* __restrict__ gamma, const float* __restrict__ beta,
    const float* __restrict__ Wk, const float* __restrict__ Wv,
    const float* __restrict__ Wg, const float* __restrict__ Wo) {
    __shared__ float tile[TS * TP];
    __shared__ __align__(16) float sWT[NC * 16];  // [c][0..7]=Wk, [c][8..15]=Wv
    __shared__ float sg[NC], sb[NC];
    __shared__ float scol[NC];                     // half-column partials

    const int i  = blockIdx.y;
    const int s0 = blockIdx.x * TS;
    const int t  = threadIdx.x;

    if (blockIdx.x == 0 && blockIdx.y == 0) {
        for (int idx = t; idx < NC * NC; idx += TS) {
            const int n = idx >> 6, k = idx & 63;
            const int dst = n * XS + k;
            const float wg = Wg[idx];
            const __nv_bfloat16 gh = __float2bfloat16(wg);
            g_wgh[dst] = gh;
            g_wgl[dst] = __float2bfloat16(wg - __bfloat162float(gh));
            const float wo = Wo[idx];
            const __nv_bfloat16 oh = __float2bfloat16(wo);
            g_woh[dst] = oh;
            g_wol[dst] = __float2bfloat16(wo - __bfloat162float(oh));
        }
    }

    for (int idx = t; idx < 8 * NC; idx += TS) {
        const int j = idx >> 6, c = idx & 63;
        sWT[c * 16 + j]     = Wk[idx];
        sWT[c * 16 + 8 + j] = Wv[idx];
    }
    if (t < NC) { sg[t] = gamma[t]; sb[t] = beta[t]; }
    for (int idx = t; idx < TS * NC / 4; idx += TS) {
        const int r = idx >> 4, c4 = (idx & 15) * 4;
        const float4 v = *(const float4*)&m[((size_t)(s0 + r) * NI + i) * NC + c4];
        tile[r * TP + c4 + 0] = v.x;
        tile[r * TP + c4 + 1] = v.y;
        tile[r * TP + c4 + 2] = v.z;
        tile[r * TP + c4 + 3] = v.w;
    }
    __syncthreads();

    float s1 = 0.f, s2 = 0.f;
#pragma unroll
    for (int c = 0; c < NC; c++) {
        const float v = tile[t * TP + c];
        s1 += v; s2 += v * v;
    }
    const float mu   = s1 * (1.f / 64.f);
    const float var  = s2 * (1.f / 64.f) - mu * mu;
    const float rstd = rsqrtf(var + 1e-5f);
    const float maskv = mask[(size_t)(s0 + t) * NI + i];
    g_mcol[(size_t)i * NS + s0 + t] = maskv;

    unsigned long long ka2[4], va2[4];
#pragma unroll
    for (int j = 0; j < 4; j++) { ka2[j] = 0ull; va2[j] = 0ull; }

#pragma unroll
    for (int c = 0; c < NC; c++) {
        const float mn = (tile[t * TP + c] - mu) * rstd * sg[c] + sb[c];
        tile[t * TP + c] = mn * maskv;
        const unsigned long long mp = pk2(mn, mn);
        const ulonglong2 wk  = *(const ulonglong2*)&sWT[c * 16];
        const ulonglong2 wk1 = *(const ulonglong2*)&sWT[c * 16 + 4];
        const ulonglong2 wv  = *(const ulonglong2*)&sWT[c * 16 + 8];
        const ulonglong2 wv1 = *(const ulonglong2*)&sWT[c * 16 + 12];
        ka2[0] = f2fma(mp, wk.x,  ka2[0]);
        ka2[1] = f2fma(mp, wk.y,  ka2[1]);
        ka2[2] = f2fma(mp, wk1.x, ka2[2]);
        ka2[3] = f2fma(mp, wk1.y, ka2[3]);
        va2[0] = f2fma(mp, wv.x,  va2[0]);
        va2[1] = f2fma(mp, wv.y,  va2[1]);
        va2[2] = f2fma(mp, wv1.x, va2[2]);
        va2[3] = f2fma(mp, wv1.y, va2[3]);
    }

    float kr[8], vr[8];
#pragma unroll
    for (int j = 0; j < 4; j++) {
        upk2(ka2[j], kr[2 * j], kr[2 * j + 1]);
        upk2(va2[j], vr[2 * j], vr[2 * j + 1]);
    }
    float4* kp = (float4*)&g_k[((size_t)i * NS + s0 + t) * 8];
    float4* vp = (float4*)&g_v[((size_t)i * NS + s0 + t) * 8];
    kp[0] = make_float4(kr[0], kr[1], kr[2], kr[3]);
    kp[1] = make_float4(kr[4], kr[5], kr[6], kr[7]);
    vp[0] = make_float4(vr[0], vr[1], vr[2], vr[3]);
    vp[1] = make_float4(vr[4], vr[5], vr[6], vr[7]);
    __syncthreads();

    // column sums: 128 threads each own a half-column (64 rows), then combine
    {
        const int c  = t & 63;
        const int rh = (t >> 6) * 64;     // 0 or 64
        float a0 = 0.f, a1 = 0.f, a2 = 0.f, a3 = 0.f;
        for (int r = rh; r < rh + 64; r += 4) {
            a0 += tile[(r + 0) * TP + c];
            a1 += tile[(r + 1) * TP + c];
            a2 += tile[(r + 2) * TP + c];
            a3 += tile[(r + 3) * TP + c];
        }
        const float half = (a0 + a1) + (a2 + a3);
        if (t < 64) scol[c] = half;
        __syncthreads();
        if (t >= 64)
            g_qpart[((size_t)blockIdx.x * NI + i) * NC + c] = scol[c] + half;
    }
}

// ==========================================================================
// Kernel 2: q projection (merged) + DOUBLE-BUFFERED smem-staged warp-per-head
// attention. grid NI, block 256 (8 warps = 8 heads). One-pass softmax.
// ==========================================================================
__global__ void __launch_bounds__(256) k_attn(const float* __restrict__ Wq) {
    __shared__ float sq[HC];
    __shared__ float sqg[NC];
    __shared__ float sden[256];
    __shared__ float sk[2][256 * KS9];
    __shared__ float sv[2][256 * KS9];
    __shared__ float smk[2][256];

    const int i = blockIdx.x;
    const int t = threadIdx.x;
    const int h = t >> 5, lane = t & 31;

    // ---- q projection prologue (merged k_q) ----
    float dsum = 0.f;
    for (int s = t; s < NS; s += 256) dsum += g_mcol[(size_t)i * NS + s];
    sden[t] = dsum;
    if (t < NC) {
        float acc = 0.f;
        for (int tt = 0; tt < NT; tt++)
            acc += g_qpart[((size_t)tt * NI + i) * NC + t];
        sqg[t] = acc;
    }
    __syncthreads();
    for (int off = 128; off >= 1; off >>= 1) {
        if (t < off) sden[t] += sden[t + off];
        __syncthreads();
    }
    const float denom = fmaxf(sden[0], 1e-5f);
    if (t < HC) {
        float q = 0.f;
#pragma unroll
        for (int c = 0; c < NC; c++) q += sqg[c] * Wq[t * NC + c];
        sq[t] = q * 0.35355339059327373f / denom;
    }
    __syncthreads();

    const float q0 = sq[h*8+0], q1 = sq[h*8+1], q2 = sq[h*8+2], q3 = sq[h*8+3];
    const float q4 = sq[h*8+4], q5 = sq[h*8+5], q6 = sq[h*8+6], q7 = sq[h*8+7];

    float esum = 0.f;
    float cacc[8];
#pragma unroll
    for (int j = 0; j < 8; j++) cacc[j] = 0.f;

    // prologue: load + store chunk 0 (mask folded to additive logit bias)
    float4 pka, pkb, pva, pvb;
    float pmk;
    {
        const float4* kg = (const float4*)&g_k[(size_t)i * NS * 8];
        const float4* vg = (const float4*)&g_v[(size_t)i * NS * 8];
        pka = kg[t * 2]; pkb = kg[t * 2 + 1];
        pva = vg[t * 2]; pvb = vg[t * 2 + 1];
        pmk = (g_mcol[(size_t)i * NS + t] > 0.f) ? 0.f : -1e9f;
        float* kd = &sk[0][t * KS9];
        float* vd = &sv[0][t * KS9];
        kd[0] = pka.x; kd[1] = pka.y; kd[2] = pka.z; kd[3] = pka.w;
        kd[4] = pkb.x; kd[5] = pkb.y; kd[6] = pkb.z; kd[7] = pkb.w;
        vd[0] = pva.x; vd[1] = pva.y; vd[2] = pva.z; vd[3] = pva.w;
        vd[4] = pvb.x; vd[5] = pvb.y; vd[6] = pvb.z; vd[7] = pvb.w;
        smk[0][t] = pmk;
    }

    const int NCHUNK = NS / 256;   // 8
#pragma unroll 1
    for (int j = 0; j < NCHUNK; j++) {
        if (j + 1 < NCHUNK) {
            const int c0 = (j + 1) * 256;
            const float4* kg = (const float4*)&g_k[((size_t)i * NS + c0) * 8];
            const float4* vg = (const float4*)&g_v[((size_t)i * NS + c0) * 8];
            pka = kg[t * 2]; pkb = kg[t * 2 + 1];
            pva = vg[t * 2]; pvb = vg[t * 2 + 1];
            pmk = (g_mcol[(size_t)i * NS + c0 + t] > 0.f) ? 0.f : -1e9f;
        }
        __syncthreads();

        const int b = j & 1;
#pragma unroll
        for (int u = 0; u < 8; u++) {
            const int s = lane + 32 * u;
            const float* kr = &sk[b][s * KS9];
            const float l = q0*kr[0] + q1*kr[1] + q2*kr[2] + q3*kr[3]
                          + q4*kr[4] + q5*kr[5] + q6*kr[6] + q7*kr[7]
                          + smk[b][s];
            const float e = __expf(l);
            esum += e;
            const float* vr = &sv[b][s * KS9];
            cacc[0] += e * vr[0]; cacc[1] += e * vr[1];
            cacc[2] += e * vr[2]; cacc[3] += e * vr[3];
            cacc[4] += e * vr[4]; cacc[5] += e * vr[5];
            cacc[6] += e * vr[6]; cacc[7] += e * vr[7];
        }

        if (j + 1 < NCHUNK) {
            const int nb = (j + 1) & 1;
            float* kd = &sk[nb][t * KS9];
            float* vd = &sv[nb][t * KS9];
            kd[0] = pka.x; kd[1] = pka.y; kd[2] = pka.z; kd[3] = pka.w;
            kd[4] = pkb.x; kd[5] = pkb.y; kd[6] = pkb.z; kd[7] = pkb.w;
            vd[0] = pva.x; vd[1] = pva.y; vd[2] = pva.z; vd[3] = pva.w;
            vd[4] = pvb.x; vd[5] = pvb.y; vd[6] = pvb.z; vd[7] = pvb.w;
            smk[nb][t] = pmk;
        }
    }

#pragma unroll
    for (int d = 16; d; d >>= 1) esum += __shfl_xor_sync(0xffffffffu, esum, d);
#pragma unroll
    for (int j = 0; j < 8; j++)
#pragma unroll
        for (int d = 16; d; d >>= 1)
            cacc[j] += __shfl_xor_sync(0xffffffffu, cacc[j], d);

    if (lane == 0) {
        const float inv = 1.f / esum;
#pragma unroll
        for (int j = 0; j < 8; j++)
            g_ctx[i * HC + h * 8 + j] = cacc[j] * inv;
    }
}

// ==========================================================================
// Kernel 3: mma.sync bf16-split  LN -> GEMM1(Wg) -> sigmoid*ctx -> GEMM2(Wo).
// grid (NT, NI), block 128. Both weight pairs resident, paired ldmatrix.x4.
// ==========================================================================
__global__ void __launch_bounds__(128) k_out(
    const float* __restrict__ m,
    const float* __restrict__ gamma, const float* __restrict__ beta,
    const float* __restrict__ bg, const float* __restrict__ bo,
    float* __restrict__ out) {
    extern __shared__ __align__(16) char smem[];
    const uint32_t sb = smem_u32(smem);
    const int t = threadIdx.x;
    const int warp = t >> 5, lane = t & 31;
    const int i  = blockIdx.y;
    const int s0 = blockIdx.x * TS;

    float* sctx = (float*)(smem + OFF_CTX);
    float* sbg  = (float*)(smem + OFF_BG);
    float* sbo  = (float*)(smem + OFF_BO);

    // copy bf16 weights (4 tiles x 9216B = 2304 uint4)
    {
        uint4* dst = (uint4*)(smem + OFF_WGH);
        const uint4* s0p = (const uint4*)g_wgh;
        const uint4* s1p = (const uint4*)g_wgl;
        const uint4* s2p = (const uint4*)g_woh;
        const uint4* s3p = (const uint4*)g_wol;
        for (int idx = t; idx < 576; idx += 128) {
            dst[idx]        = s0p[idx];
            dst[576 + idx]  = s1p[idx];
            dst[1152 + idx] = s2p[idx];
            dst[1728 + idx] = s3p[idx];
        }
    }
    if (t < 64) {
        sctx[t] = g_ctx[i * HC + t];
        sbg[t]  = bg[t];
        sbo[t]  = bo[t];
    }

    // LN on own row, bf16 hi/lo into X tiles — packed STS.128 (conflict-free)
    {
        const float* mr = &m[((size_t)(s0 + t) * NI + i) * NC];
        float x[NC];
        float s1 = 0.f, s2 = 0.f;
#pragma unroll
        for (int c4 = 0; c4 < NC; c4 += 4) {
            const float4 v = *(const float4*)&mr[c4];
            x[c4] = v.x; x[c4+1] = v.y; x[c4+2] = v.z; x[c4+3] = v.w;
            s1 += v.x + v.y + v.z + v.w;
            s2 += v.x*v.x + v.y*v.y + v.z*v.z + v.w*v.w;
        }
        const float mu   = s1 * (1.f / 64.f);
        const float var  = s2 * (1.f / 64.f) - mu * mu;
        const float rstd = rsqrtf(var + 1e-5f);
#pragma unroll
        for (int c = 0; c < NC; c++)
            x[c] = (x[c] - mu) * rstd * gamma[c] + beta[c];
#pragma unroll
        for (int c = 0; c < NC; c += 8) {
            uint32_t hw[4], lw[4];
#pragma unroll
            for (int j = 0; j < 4; j++) {
                const float x0 = x[c + 2*j], x1 = x[c + 2*j + 1];
                __nv_bfloat162 hp;
                hp.x = __float2bfloat16(x0);
                hp.y = __float2bfloat16(x1);
                hw[j] = *(uint32_t*)&hp;
                __nv_bfloat162 lp;
                lp.x = __float2bfloat16(x0 - __bfloat162float(hp.x));
                lp.y = __float2bfloat16(x1 - __bfloat162float(hp.y));
                lw[j] = *(uint32_t*)&lp;
            }
            *(uint4*)(smem + OFF_XHI + (t * XS + c) * 2) =
                make_uint4(hw[0], hw[1], hw[2], hw[3]);
            *(uint4*)(smem + OFF_XLO + (t * XS + c) * 2) =
                make_uint4(lw[0], lw[1], lw[2], lw[3]);
        }
    }
    __syncthreads();

    float acc[2][8][4];
#pragma unroll
    for (int mt = 0; mt < 2; mt++)
#pragma unroll
        for (int nt = 0; nt < 8; nt++)
#pragma unroll
            for (int p = 0; p < 4; p++) acc[mt][nt][p] = 0.f;

    // ---------------- GEMM1: G = X @ Wg^T ----------------
    gemm_bf16_split(sb + OFF_XHI, sb + OFF_XLO, sb + OFF_WGH, sb + OFF_WGL,
                    warp, lane, acc);
    __syncthreads();   // all ldmatrix reads of X done before overwrite

    // gate: o = ctx * sigmoid(d + bg); write O hi/lo back into X tiles
    {
        const int tr = lane >> 2;
        const int tc = (lane & 3) * 2;
#pragma unroll
        for (int mt = 0; mt < 2; mt++) {
#pragma unroll
            for (int nt = 0; nt < 8; nt++) {
                const int c0 = nt * 8 + tc;
                const float cx0 = sctx[c0], cx1 = sctx[c0 + 1];
                const float b0 = sbg[c0],  b1 = sbg[c0 + 1];
#pragma unroll
                for (int half = 0; half < 2; half++) {
                    const int r = warp * 32 + mt * 16 + tr + half * 8;
                    const float d0 = acc[mt][nt][half * 2]     + b0;
                    const float d1 = acc[mt][nt][half * 2 + 1] + b1;
                    const float o0 = cx0 * __fdividef(1.f, 1.f + __expf(-d0));
                    const float o1 = cx1 * __fdividef(1.f, 1.f + __expf(-d1));
                    __nv_bfloat162 hp;
                    hp.x = __float2bfloat16(o0);
                    hp.y = __float2bfloat16(o1);
                    *(__nv_bfloat162*)(smem + OFF_XHI + (r * XS + c0) * 2) = hp;
                    __nv_bfloat162 lp;
                    lp.x = __float2bfloat16(o0 - __bfloat162float(hp.x));
                    lp.y = __float2bfloat16(o1 - __bfloat162float(hp.y));
                    *(__nv_bfloat162*)(smem + OFF_XLO + (r * XS + c0) * 2) = lp;
                }
            }
        }
    }
    __syncthreads();

#pragma unroll
    for (int mt = 0; mt < 2; mt++)
#pragma unroll
        for (int nt = 0; nt < 8; nt++)
#pragma unroll
            for (int p = 0; p < 4; p++) acc[mt][nt][p] = 0.f;

    // ---------------- GEMM2: out = O @ Wo^T + bo ----------------
    gemm_bf16_split(sb + OFF_XHI, sb + OFF_XLO, sb + OFF_WOH, sb + OFF_WOL,
                    warp, lane, acc);

    // epilogue: + bo, store float2 per fragment element pair
    {
        const int tr = lane >> 2;
        const int tc = (lane & 3) * 2;
#pragma unroll
        for (int mt = 0; mt < 2; mt++) {
#pragma unroll
            for (int nt = 0; nt < 8; nt++) {
                const int c0 = nt * 8 + tc;
                const float b0 = sbo[c0], b1 = sbo[c0 + 1];
#pragma unroll
                for (int half = 0; half < 2; half++) {
                    const int r = warp * 32 + mt * 16 + tr + half * 8;
                    float2 v;
                    v.x = acc[mt][nt][half * 2]     + b0;
                    v.y = acc[mt][nt][half * 2 + 1] + b1;
                    *(float2*)&out[((size_t)(s0 + r) * NI + i) * NC + c0] = v;
                }
            }
        }
    }
}

// ==========================================================================
extern "C" void kernel_launch(void* const* d_in, const int* in_sizes, int n_in,
                              void* d_out, int out_size) {
    const float* m     = (const float*)d_in[0];
    const float* mask  = (const float*)d_in[1];
    const float* gamma = (const float*)d_in[2];
    const float* beta  = (const float*)d_in[3];
    const float* Wq    = (const float*)d_in[4];
    const float* Wk    = (const float*)d_in[5];
    const float* Wv    = (const float*)d_in[6];
    const float* Wg    = (const float*)d_in[7];
    const float* bg    = (const float*)d_in[8];
    const float* Wo    = (const float*)d_in[9];
    const float* bo    = (const float*)d_in[10];
    float* out = (float*)d_out;

    cudaFuncSetAttribute(k_out, cudaFuncAttributeMaxDynamicSharedMemorySize,
                         SMEM_TOTAL_OUT);

    dim3 g1(NT, NI);
    k_pass1<<<g1, TS>>>(m, mask, gamma, beta, Wk, Wv, Wg, Wo);
    k_attn<<<NI, 256>>>(Wq);
    dim3 g4(NT, NI);
    k_out<<<g4, 128, SMEM_TOTAL_OUT>>>(m, gamma, beta, bg, bo, out);
}